// round 13
// baseline (speedup 1.0000x reference)
#include <cuda_runtime.h>
#include <cuda_fp16.h>
#include <cstdint>

// ---------------------------------------------------------------------------
// Scratch (device globals)
// ---------------------------------------------------------------------------
__device__ __half g_q [2u * 2048u * 1024u];
__device__ __half g_k [2u * 2048u * 1024u];
__device__ __half g_v [2u * 2048u * 1024u];
__device__ __half g_yt[2u * 2048u * 1024u];
__device__ __half g_xh   [4096u * 1024u];
__device__ __half g_wqkvh[1024u * 3072u];
__device__ __half g_wprojh[1024u * 1024u];

// ---------------------------------------------------------------------------
// cp.async helpers
// ---------------------------------------------------------------------------
__device__ __forceinline__ uint32_t smem_u32(const void* p) {
    return (uint32_t)__cvta_generic_to_shared(p);
}
__device__ __forceinline__ void cp16(uint32_t dst, const void* src) {
    asm volatile("cp.async.cg.shared.global [%0], [%1], 16;"
                 :: "r"(dst), "l"(src) : "memory");
}
__device__ __forceinline__ void cp_commit() {
    asm volatile("cp.async.commit_group;" ::: "memory");
}
template <int N>
__device__ __forceinline__ void cp_wait() {
    asm volatile("cp.async.wait_group %0;" :: "n"(N) : "memory");
}

// ---------------------------------------------------------------------------
// mma / ldmatrix helpers
// ---------------------------------------------------------------------------
__device__ __forceinline__ void mma16816(float* c, const uint32_t* a,
                                         uint32_t b0, uint32_t b1) {
    asm volatile(
        "mma.sync.aligned.m16n8k16.row.col.f32.f16.f16.f32 "
        "{%0,%1,%2,%3}, {%4,%5,%6,%7}, {%8,%9}, {%0,%1,%2,%3};"
        : "+f"(c[0]), "+f"(c[1]), "+f"(c[2]), "+f"(c[3])
        : "r"(a[0]), "r"(a[1]), "r"(a[2]), "r"(a[3]), "r"(b0), "r"(b1));
}
__device__ __forceinline__ void ldsm4(uint32_t& r0, uint32_t& r1,
                                      uint32_t& r2, uint32_t& r3, uint32_t a) {
    asm volatile("ldmatrix.sync.aligned.m8n8.x4.shared.b16 {%0,%1,%2,%3}, [%4];"
                 : "=r"(r0), "=r"(r1), "=r"(r2), "=r"(r3) : "r"(a));
}
__device__ __forceinline__ void ldsm4t(uint32_t& r0, uint32_t& r1,
                                       uint32_t& r2, uint32_t& r3, uint32_t a) {
    asm volatile("ldmatrix.sync.aligned.m8n8.x4.trans.shared.b16 {%0,%1,%2,%3}, [%4];"
                 : "=r"(r0), "=r"(r1), "=r"(r2), "=r"(r3) : "r"(a));
}

// ---------------------------------------------------------------------------
// Combined fp32 -> fp16 conversion (x, Wqkv, Wproj in one launch)
// ---------------------------------------------------------------------------
#define N8_X  (4096u * 1024u / 8u)
#define N8_WQ (1024u * 3072u / 8u)
#define N8_WP (1024u * 1024u / 8u)

__global__ void to_half3_kernel(const float* __restrict__ x,
                                const float* __restrict__ wq,
                                const float* __restrict__ wp,
                                __half* __restrict__ xh,
                                __half* __restrict__ wqh,
                                __half* __restrict__ wph)
{
    uint32_t i = blockIdx.x * blockDim.x + threadIdx.x;
    const float* in;
    __half* out;
    uint32_t j;
    if (i < N8_X)                { in = x;  out = xh;  j = i; }
    else if (i < N8_X + N8_WQ)   { in = wq; out = wqh; j = i - N8_X; }
    else if (i < N8_X + N8_WQ + N8_WP) { in = wp; out = wph; j = i - N8_X - N8_WQ; }
    else return;
    float4 a = ((const float4*)in)[j * 2];
    float4 b = ((const float4*)in)[j * 2 + 1];
    __half h[8];
    h[0] = __float2half_rn(a.x); h[1] = __float2half_rn(a.y);
    h[2] = __float2half_rn(a.z); h[3] = __float2half_rn(a.w);
    h[4] = __float2half_rn(b.x); h[5] = __float2half_rn(b.y);
    h[6] = __float2half_rn(b.z); h[7] = __float2half_rn(b.w);
    ((uint4*)out)[j] = *(uint4*)h;
}

// ---------------------------------------------------------------------------
// FP16 raw-mma GEMM (fp32 accumulate), BK=64, 3-stage cp.async, 2 CTAs/SM,
// register-level fragment double-buffering (LDSM of ks+1 overlaps HMMA of ks).
// C = (A[M,K] @ B[K,N] + bias[N]) [* 0.125 for the Q output buffer]
// ---------------------------------------------------------------------------
#define G_ALD 72
#define G_BLD 136
#define G_ASZ (128 * G_ALD)
#define G_BSZ (64 * G_BLD)
#define G_STG 3
#define G_SMEM_BYTES (G_STG * (G_ASZ + G_BSZ) * 2)   // 107520

template <int ROUND_OUT>
__global__ __launch_bounds__(256, 2) void gemm_mma_kernel(
    const __half* __restrict__ A, const __half* __restrict__ B,
    const float* __restrict__ bias,
    void* __restrict__ out0v, void* __restrict__ out1v, void* __restrict__ out2v,
    int M, int N, int K)
{
    extern __shared__ char gsmc[];
    __half* gsm = (__half*)gsmc;
    const uint32_t smb = smem_u32(gsmc);

    const int tid  = threadIdx.x;
    const int wid  = tid >> 5;
    const int lane = tid & 31;
    const int wmi  = wid & 3;
    const int wni  = wid >> 2;
    const int m0   = blockIdx.y * 128;
    const int n0   = blockIdx.x * 128;

    const int a_row = (lane & 15);
    const int a_col = (lane >> 4) << 3;
    const int b_row = (lane & 7) + (((lane >> 3) & 1) << 3);
    const int b_col = (lane >> 4) << 3;

    float cfr[2][8][4];
#pragma unroll
    for (int mi = 0; mi < 2; ++mi)
#pragma unroll
        for (int nt = 0; nt < 8; ++nt)
#pragma unroll
            for (int j = 0; j < 4; ++j) cfr[mi][nt][j] = 0.0f;

    const int iters = K >> 6;

    auto issue_stage = [&](int stage) {
        const int s = stage % G_STG;
        const int k0 = stage << 6;
        __half* as = gsm + s * G_ASZ;
        __half* bs = gsm + G_STG * G_ASZ + s * G_BSZ;
#pragma unroll
        for (int t = 0; t < 4; ++t) {
            int f = tid + t * 256;
            int r = f >> 3, c8 = (f & 7) << 3;
            cp16(smem_u32(as + r * G_ALD + c8),
                 A + (size_t)(m0 + r) * K + k0 + c8);
        }
#pragma unroll
        for (int t = 0; t < 4; ++t) {
            int f = tid + t * 256;
            int r = f >> 4, c8 = (f & 15) << 3;
            cp16(smem_u32(bs + r * G_BLD + c8),
                 B + (size_t)(k0 + r) * N + n0 + c8);
        }
        cp_commit();
    };

    issue_stage(0);
    issue_stage(1);

    uint32_t af[2][2][4];    // [pipe buf][mi][4]
    uint32_t bf[2][4][4];    // [pipe buf][p][4]

    for (int it = 0; it < iters; ++it) {
        cp_wait<1>();
        __syncthreads();

        if (it + 2 < iters) issue_stage(it + 2);
        else                cp_commit();

        const int s = it % G_STG;
        const uint32_t a_base = smb + (s * G_ASZ
                              + (wmi * 32 + a_row) * G_ALD + a_col) * 2;
        const uint32_t b_base = smb + (G_STG * G_ASZ + s * G_BSZ
                              + b_row * G_BLD + wni * 64 + b_col) * 2;

        // prologue: load ks=0 fragments into pipe buf 0
#pragma unroll
        for (int mi = 0; mi < 2; ++mi)
            ldsm4(af[0][mi][0], af[0][mi][1], af[0][mi][2], af[0][mi][3],
                  a_base + (mi * 16 * G_ALD) * 2);
#pragma unroll
        for (int p = 0; p < 4; ++p)
            ldsm4t(bf[0][p][0], bf[0][p][1], bf[0][p][2], bf[0][p][3],
                   b_base + (p * 16) * 2);

#pragma unroll
        for (int ks = 0; ks < 4; ++ks) {
            const int cur = ks & 1;
            const int nxt = cur ^ 1;
            if (ks < 3) {   // prefetch ks+1 fragments (overlaps the mmas below)
#pragma unroll
                for (int mi = 0; mi < 2; ++mi)
                    ldsm4(af[nxt][mi][0], af[nxt][mi][1], af[nxt][mi][2], af[nxt][mi][3],
                          a_base + (mi * 16 * G_ALD + (ks + 1) * 16) * 2);
#pragma unroll
                for (int p = 0; p < 4; ++p)
                    ldsm4t(bf[nxt][p][0], bf[nxt][p][1], bf[nxt][p][2], bf[nxt][p][3],
                           b_base + ((ks + 1) * 16 * G_BLD + p * 16) * 2);
            }
#pragma unroll
            for (int mi = 0; mi < 2; ++mi)
#pragma unroll
                for (int p = 0; p < 4; ++p) {
                    mma16816(cfr[mi][2 * p],     af[cur][mi], bf[cur][p][0], bf[cur][p][1]);
                    mma16816(cfr[mi][2 * p + 1], af[cur][mi], bf[cur][p][2], bf[cur][p][3]);
                }
        }
    }

    // ---- Epilogue: bias (+ 0.125 scale for the Q buffer) + store ----
    const int nc = n0 & 1023;
    const int colw = wni * 64 + 2 * (lane & 3);
    float2 bv[8];
#pragma unroll
    for (int nt = 0; nt < 8; ++nt) {
        bv[nt].x = bias[n0 + colw + nt * 8];
        bv[nt].y = bias[n0 + colw + nt * 8 + 1];
    }
    const int row0 = m0 + wmi * 32 + (lane >> 2);

    if (ROUND_OUT) {
        __half* outp = (n0 < 1024) ? (__half*)out0v
                     : ((n0 < 2048) ? (__half*)out1v : (__half*)out2v);
        const float osc = (n0 < 1024) ? 0.125f : 1.0f;
#pragma unroll
        for (int mi = 0; mi < 2; ++mi) {
#pragma unroll
            for (int nt = 0; nt < 8; ++nt) {
                int col = nc + colw + nt * 8;
                __half2 v0 = __floats2half2_rn((cfr[mi][nt][0] + bv[nt].x) * osc,
                                               (cfr[mi][nt][1] + bv[nt].y) * osc);
                __half2 v1 = __floats2half2_rn((cfr[mi][nt][2] + bv[nt].x) * osc,
                                               (cfr[mi][nt][3] + bv[nt].y) * osc);
                *(__half2*)(outp + (size_t)(row0 + mi * 16) * 1024 + col) = v0;
                *(__half2*)(outp + (size_t)(row0 + mi * 16 + 8) * 1024 + col) = v1;
            }
        }
    } else {
        float* outp = (n0 < 1024) ? (float*)out0v
                    : ((n0 < 2048) ? (float*)out1v : (float*)out2v);
#pragma unroll
        for (int mi = 0; mi < 2; ++mi) {
#pragma unroll
            for (int nt = 0; nt < 8; ++nt) {
                int col = nc + colw + nt * 8;
                float2 v0 = { cfr[mi][nt][0] + bv[nt].x, cfr[mi][nt][1] + bv[nt].y };
                float2 v1 = { cfr[mi][nt][2] + bv[nt].x, cfr[mi][nt][3] + bv[nt].y };
                *(float2*)(outp + (size_t)(row0 + mi * 16) * 1024 + col) = v0;
                *(float2*)(outp + (size_t)(row0 + mi * 16 + 8) * 1024 + col) = v1;
            }
        }
    }
}

// ---------------------------------------------------------------------------
// Flash attention (causal), FA2-style. Br=128, Bc=64, hd=64, 256 thr.
// Q pre-scaled by GEMM1. Q + 3-deep K/V pipeline all via cp.async. (unchanged)
// ---------------------------------------------------------------------------
#define FLD 72
#define FQ_OFF  0
#define FK_OFF  18432
#define FV_OFF  (18432 + 27648)
#define F_SMEM  (18432 + 2 * 27648)  // 73728

__global__ __launch_bounds__(256) void flash_fa2_kernel(
    const __half* __restrict__ Qg, const __half* __restrict__ Kg,
    const __half* __restrict__ Vg, __half* __restrict__ yt)
{
    extern __shared__ char smc[];
    const uint32_t smb = smem_u32(smc);
    const uint32_t kbA[3] = { smb + FK_OFF, smb + FK_OFF + 9216, smb + FK_OFF + 18432 };
    const uint32_t vbA[3] = { smb + FV_OFF, smb + FV_OFF + 9216, smb + FV_OFF + 18432 };

    const int qt   = gridDim.x - 1 - blockIdx.x;
    const int bh   = blockIdx.y;
    const int tid  = threadIdx.x;
    const int w    = tid >> 5;
    const int lane = tid & 31;

    const int q_row = (lane & 15);
    const int q_col = (lane >> 4) << 3;
    const int k_row = (lane & 7) + ((lane >> 4) << 3);
    const int k_col = ((lane >> 3) & 1) << 3;
    const int v_row = (lane & 7) + (((lane >> 3) & 1) << 3);
    const int v_col = (lane >> 4) << 3;

    const size_t head_off = (size_t)bh * 131072u;
    const __half* qg = Qg + head_off + (size_t)qt * 8192u;
    const __half* kg = Kg + head_off;
    const __half* vg = Vg + head_off;

#pragma unroll
    for (int t = 0; t < 4; ++t) {
        int f = tid + t * 256;
        int rr = f >> 3, c8 = (f & 7) << 3;
        cp16(smb + FQ_OFF + (rr * FLD + c8) * 2, qg + rr * 64 + c8);
    }
    cp_commit();

    auto issue_kv = [&](int kt) {
        const int buf = kt % 3;
        const __half* kp = kg + (size_t)kt * 4096u;
        const __half* vp = vg + (size_t)kt * 4096u;
#pragma unroll
        for (int t = 0; t < 2; ++t) {
            int f = tid + t * 256;
            int rr = f >> 3, c8 = (f & 7) << 3;
            cp16(kbA[buf] + (rr * FLD + c8) * 2, kp + rr * 64 + c8);
            cp16(vbA[buf] + (rr * FLD + c8) * 2, vp + rr * 64 + c8);
        }
        cp_commit();
    };

    const int n_kt = 2 * (qt + 1);
    issue_kv(0);
    issue_kv(1);

    cp_wait<2>();
    __syncthreads();

    uint32_t qf[4][4];
#pragma unroll
    for (int kk = 0; kk < 4; ++kk) {
        uint32_t a = smb + FQ_OFF
                   + ((w * 16 + q_row) * FLD + kk * 16 + q_col) * 2;
        ldsm4(qf[kk][0], qf[kk][1], qf[kk][2], qf[kk][3], a);
    }

    float oacc[8][4];
#pragma unroll
    for (int nt = 0; nt < 8; ++nt)
#pragma unroll
        for (int j = 0; j < 4; ++j) oacc[nt][j] = 0.0f;
    float m_lo = -1e30f, m_hi = -1e30f;
    float l_lo = 0.0f,   l_hi = 0.0f;

    const int row_g_lo = qt * 128 + w * 16 + (lane >> 2);
    const int row_g_hi = row_g_lo + 8;

    for (int kt = 0; kt < n_kt; ++kt) {
        const int buf = kt % 3;
        cp_wait<1>();
        __syncthreads();
        if (kt + 2 < n_kt) issue_kv(kt + 2);
        else               cp_commit();

        float sacc[8][4];
#pragma unroll
        for (int nt = 0; nt < 8; ++nt)
#pragma unroll
            for (int j = 0; j < 4; ++j) sacc[nt][j] = 0.0f;
#pragma unroll
        for (int p = 0; p < 4; ++p) {
#pragma unroll
            for (int kk = 0; kk < 4; ++kk) {
                uint32_t b0, b1, b2, b3;
                uint32_t a = kbA[buf]
                           + ((p * 16 + k_row) * FLD + kk * 16 + k_col) * 2;
                ldsm4(b0, b1, b2, b3, a);
                mma16816(sacc[2 * p],     qf[kk], b0, b1);
                mma16816(sacc[2 * p + 1], qf[kk], b2, b3);
            }
        }

        if (kt >= 2 * qt) {
            const int cb = kt * 64 + 2 * (lane & 3);
#pragma unroll
            for (int nt = 0; nt < 8; ++nt) {
                int c = cb + nt * 8;
                if (c     > row_g_lo) sacc[nt][0] = -1e30f;
                if (c + 1 > row_g_lo) sacc[nt][1] = -1e30f;
                if (c     > row_g_hi) sacc[nt][2] = -1e30f;
                if (c + 1 > row_g_hi) sacc[nt][3] = -1e30f;
            }
        }

        float mx_lo = -1e30f, mx_hi = -1e30f;
#pragma unroll
        for (int nt = 0; nt < 8; ++nt) {
            mx_lo = fmaxf(mx_lo, fmaxf(sacc[nt][0], sacc[nt][1]));
            mx_hi = fmaxf(mx_hi, fmaxf(sacc[nt][2], sacc[nt][3]));
        }
        mx_lo = fmaxf(mx_lo, __shfl_xor_sync(0xffffffffu, mx_lo, 1));
        mx_lo = fmaxf(mx_lo, __shfl_xor_sync(0xffffffffu, mx_lo, 2));
        mx_hi = fmaxf(mx_hi, __shfl_xor_sync(0xffffffffu, mx_hi, 1));
        mx_hi = fmaxf(mx_hi, __shfl_xor_sync(0xffffffffu, mx_hi, 2));

        const float mn_lo = fmaxf(m_lo, mx_lo);
        const float mn_hi = fmaxf(m_hi, mx_hi);
        const float al_lo = __expf(m_lo - mn_lo);
        const float al_hi = __expf(m_hi - mn_hi);
        m_lo = mn_lo; m_hi = mn_hi;

        float sum_lo = 0.0f, sum_hi = 0.0f;
        uint32_t pfr[4][4];
#pragma unroll
        for (int nt = 0; nt < 8; ++nt) {
            float p0 = __expf(sacc[nt][0] - mn_lo);
            float p1 = __expf(sacc[nt][1] - mn_lo);
            float p2 = __expf(sacc[nt][2] - mn_hi);
            float p3 = __expf(sacc[nt][3] - mn_hi);
            sum_lo += p0 + p1;
            sum_hi += p2 + p3;
            __half2 h01 = __floats2half2_rn(p0, p1);
            __half2 h23 = __floats2half2_rn(p2, p3);
            pfr[nt >> 1][(nt & 1) * 2 + 0] = *(uint32_t*)&h01;
            pfr[nt >> 1][(nt & 1) * 2 + 1] = *(uint32_t*)&h23;
        }
        l_lo = l_lo * al_lo + sum_lo;
        l_hi = l_hi * al_hi + sum_hi;

#pragma unroll
        for (int nt = 0; nt < 8; ++nt) {
            oacc[nt][0] *= al_lo; oacc[nt][1] *= al_lo;
            oacc[nt][2] *= al_hi; oacc[nt][3] *= al_hi;
        }

#pragma unroll
        for (int p = 0; p < 4; ++p) {
#pragma unroll
            for (int t = 0; t < 4; ++t) {
                uint32_t b0, b1, b2, b3;
                uint32_t a = vbA[buf]
                           + ((t * 16 + v_row) * FLD + p * 16 + v_col) * 2;
                ldsm4t(b0, b1, b2, b3, a);
                mma16816(oacc[2 * p],     pfr[t], b0, b1);
                mma16816(oacc[2 * p + 1], pfr[t], b2, b3);
            }
        }
    }

    l_lo += __shfl_xor_sync(0xffffffffu, l_lo, 1);
    l_lo += __shfl_xor_sync(0xffffffffu, l_lo, 2);
    l_hi += __shfl_xor_sync(0xffffffffu, l_hi, 1);
    l_hi += __shfl_xor_sync(0xffffffffu, l_hi, 2);
    const float inv_lo = 1.0f / l_lo;
    const float inv_hi = 1.0f / l_hi;

    const int b = bh >> 4;
    const int h = bh & 15;
    const int tq_lo = qt * 128 + w * 16 + (lane >> 2);
    __half* dst_lo = yt + ((size_t)(b * 2048 + tq_lo)) * 1024u + h * 64 + 2 * (lane & 3);
    __half* dst_hi = dst_lo + 8u * 1024u;
#pragma unroll
    for (int nt = 0; nt < 8; ++nt) {
        __half2 vlo = __floats2half2_rn(oacc[nt][0] * inv_lo, oacc[nt][1] * inv_lo);
        __half2 vhi = __floats2half2_rn(oacc[nt][2] * inv_hi, oacc[nt][3] * inv_hi);
        *(__half2*)(dst_lo + nt * 8) = vlo;
        *(__half2*)(dst_hi + nt * 8) = vhi;
    }
}

// ---------------------------------------------------------------------------
// Launch
// ---------------------------------------------------------------------------
extern "C" void kernel_launch(void* const* d_in, const int* in_sizes, int n_in,
                              void* d_out, int out_size)
{
    const float* x     = (const float*)d_in[0];
    const float* Wqkv  = (const float*)d_in[1];
    const float* bqkv  = (const float*)d_in[2];
    const float* Wproj = (const float*)d_in[3];
    const float* bproj = (const float*)d_in[4];
    float* out = (float*)d_out;

    __half *q, *k, *v, *yt, *xh, *wqkvh, *wprojh;
    cudaGetSymbolAddress((void**)&q,  g_q);
    cudaGetSymbolAddress((void**)&k,  g_k);
    cudaGetSymbolAddress((void**)&v,  g_v);
    cudaGetSymbolAddress((void**)&yt, g_yt);
    cudaGetSymbolAddress((void**)&xh, g_xh);
    cudaGetSymbolAddress((void**)&wqkvh, g_wqkvh);
    cudaGetSymbolAddress((void**)&wprojh, g_wprojh);

    const int M = 4096, C = 1024;

    // 0) fp32 -> fp16 conversion (single launch)
    {
        uint32_t total = N8_X + N8_WQ + N8_WP;
        to_half3_kernel<<<(total + 255) / 256, 256>>>(x, Wqkv, Wproj,
                                                      xh, wqkvh, wprojh);
    }

    cudaFuncSetAttribute(gemm_mma_kernel<1>,
                         cudaFuncAttributeMaxDynamicSharedMemorySize, G_SMEM_BYTES);
    cudaFuncSetAttribute(gemm_mma_kernel<0>,
                         cudaFuncAttributeMaxDynamicSharedMemorySize, G_SMEM_BYTES);

    // 1) QKV projection -> half q/k/v (Q pre-scaled by 0.125)
    {
        dim3 grid(3 * C / 128, M / 128);   // (24, 32)
        gemm_mma_kernel<1><<<grid, 256, G_SMEM_BYTES>>>(xh, wqkvh, bqkv,
                                                        q, k, v, M, 3 * C, C);
    }

    // 2) Flash attention (causal) -> yt (half)
    {
        cudaFuncSetAttribute(flash_fa2_kernel,
                             cudaFuncAttributeMaxDynamicSharedMemorySize, F_SMEM);
        dim3 grid(2048 / 128, 32);         // (16, 32)
        flash_fa2_kernel<<<grid, 256, F_SMEM>>>(q, k, v, yt);
    }

    // 3) Output projection -> fp32 out
    {
        dim3 grid(C / 128, M / 128);       // (8, 32)
        gemm_mma_kernel<0><<<grid, 256, G_SMEM_BYTES>>>(yt, wprojh, bproj,
                                                        out, out, out, M, C, C);
    }
}

// round 14
// speedup vs baseline: 1.0469x; 1.0469x over previous
#include <cuda_runtime.h>
#include <cuda_fp16.h>
#include <cstdint>

// ---------------------------------------------------------------------------
// Scratch (device globals)
// ---------------------------------------------------------------------------
__device__ __half g_q [2u * 2048u * 1024u];
__device__ __half g_k [2u * 2048u * 1024u];
__device__ __half g_v [2u * 2048u * 1024u];
__device__ __half g_yt[2u * 2048u * 1024u];
__device__ __half g_xh   [4096u * 1024u];
__device__ __half g_wqkvh[1024u * 3072u];
__device__ __half g_wprojh[1024u * 1024u];

// ---------------------------------------------------------------------------
// cp.async helpers
// ---------------------------------------------------------------------------
__device__ __forceinline__ uint32_t smem_u32(const void* p) {
    return (uint32_t)__cvta_generic_to_shared(p);
}
__device__ __forceinline__ void cp16(uint32_t dst, const void* src) {
    asm volatile("cp.async.cg.shared.global [%0], [%1], 16;"
                 :: "r"(dst), "l"(src) : "memory");
}
__device__ __forceinline__ void cp_commit() {
    asm volatile("cp.async.commit_group;" ::: "memory");
}
template <int N>
__device__ __forceinline__ void cp_wait() {
    asm volatile("cp.async.wait_group %0;" :: "n"(N) : "memory");
}

// ---------------------------------------------------------------------------
// mma / ldmatrix helpers
// ---------------------------------------------------------------------------
__device__ __forceinline__ void mma16816(float* c, const uint32_t* a,
                                         uint32_t b0, uint32_t b1) {
    asm volatile(
        "mma.sync.aligned.m16n8k16.row.col.f32.f16.f16.f32 "
        "{%0,%1,%2,%3}, {%4,%5,%6,%7}, {%8,%9}, {%0,%1,%2,%3};"
        : "+f"(c[0]), "+f"(c[1]), "+f"(c[2]), "+f"(c[3])
        : "r"(a[0]), "r"(a[1]), "r"(a[2]), "r"(a[3]), "r"(b0), "r"(b1));
}
__device__ __forceinline__ void ldsm4(uint32_t& r0, uint32_t& r1,
                                      uint32_t& r2, uint32_t& r3, uint32_t a) {
    asm volatile("ldmatrix.sync.aligned.m8n8.x4.shared.b16 {%0,%1,%2,%3}, [%4];"
                 : "=r"(r0), "=r"(r1), "=r"(r2), "=r"(r3) : "r"(a));
}
__device__ __forceinline__ void ldsm4t(uint32_t& r0, uint32_t& r1,
                                       uint32_t& r2, uint32_t& r3, uint32_t a) {
    asm volatile("ldmatrix.sync.aligned.m8n8.x4.trans.shared.b16 {%0,%1,%2,%3}, [%4];"
                 : "=r"(r0), "=r"(r1), "=r"(r2), "=r"(r3) : "r"(a));
}

// ---------------------------------------------------------------------------
// Combined fp32 -> fp16 conversion (x, Wqkv, Wproj in one launch)
// ---------------------------------------------------------------------------
#define N8_X  (4096u * 1024u / 8u)
#define N8_WQ (1024u * 3072u / 8u)
#define N8_WP (1024u * 1024u / 8u)

__global__ void to_half3_kernel(const float* __restrict__ x,
                                const float* __restrict__ wq,
                                const float* __restrict__ wp,
                                __half* __restrict__ xh,
                                __half* __restrict__ wqh,
                                __half* __restrict__ wph)
{
    uint32_t i = blockIdx.x * blockDim.x + threadIdx.x;
    const float* in;
    __half* out;
    uint32_t j;
    if (i < N8_X)                { in = x;  out = xh;  j = i; }
    else if (i < N8_X + N8_WQ)   { in = wq; out = wqh; j = i - N8_X; }
    else if (i < N8_X + N8_WQ + N8_WP) { in = wp; out = wph; j = i - N8_X - N8_WQ; }
    else return;
    float4 a = ((const float4*)in)[j * 2];
    float4 b = ((const float4*)in)[j * 2 + 1];
    __half h[8];
    h[0] = __float2half_rn(a.x); h[1] = __float2half_rn(a.y);
    h[2] = __float2half_rn(a.z); h[3] = __float2half_rn(a.w);
    h[4] = __float2half_rn(b.x); h[5] = __float2half_rn(b.y);
    h[6] = __float2half_rn(b.z); h[7] = __float2half_rn(b.w);
    ((uint4*)out)[j] = *(uint4*)h;
}

// ---------------------------------------------------------------------------
// FP16 raw-mma GEMM (fp32 accumulate), BK=64, 3-stage cp.async, 2 CTAs/SM.
// (round-12 body — best measured GEMM). Q output scaled by 0.125*log2(e)
// so flash can use exp2.
// ---------------------------------------------------------------------------
#define G_ALD 72
#define G_BLD 136
#define G_ASZ (128 * G_ALD)
#define G_BSZ (64 * G_BLD)
#define G_STG 3
#define G_SMEM_BYTES (G_STG * (G_ASZ + G_BSZ) * 2)   // 107520

#define Q_SCALE (0.125f * 1.44269504088896340736f)

template <int ROUND_OUT>
__global__ __launch_bounds__(256, 2) void gemm_mma_kernel(
    const __half* __restrict__ A, const __half* __restrict__ B,
    const float* __restrict__ bias,
    void* __restrict__ out0v, void* __restrict__ out1v, void* __restrict__ out2v,
    int M, int N, int K)
{
    extern __shared__ char gsmc[];
    __half* gsm = (__half*)gsmc;
    const uint32_t smb = smem_u32(gsmc);

    const int tid  = threadIdx.x;
    const int wid  = tid >> 5;
    const int lane = tid & 31;
    const int wmi  = wid & 3;
    const int wni  = wid >> 2;
    const int m0   = blockIdx.y * 128;
    const int n0   = blockIdx.x * 128;

    const int a_row = (lane & 15);
    const int a_col = (lane >> 4) << 3;
    const int b_row = (lane & 7) + (((lane >> 3) & 1) << 3);
    const int b_col = (lane >> 4) << 3;

    float cfr[2][8][4];
#pragma unroll
    for (int mi = 0; mi < 2; ++mi)
#pragma unroll
        for (int nt = 0; nt < 8; ++nt)
#pragma unroll
            for (int j = 0; j < 4; ++j) cfr[mi][nt][j] = 0.0f;

    const int iters = K >> 6;

    auto issue_stage = [&](int stage) {
        const int s = stage % G_STG;
        const int k0 = stage << 6;
        __half* as = gsm + s * G_ASZ;
        __half* bs = gsm + G_STG * G_ASZ + s * G_BSZ;
#pragma unroll
        for (int t = 0; t < 4; ++t) {
            int f = tid + t * 256;
            int r = f >> 3, c8 = (f & 7) << 3;
            cp16(smem_u32(as + r * G_ALD + c8),
                 A + (size_t)(m0 + r) * K + k0 + c8);
        }
#pragma unroll
        for (int t = 0; t < 4; ++t) {
            int f = tid + t * 256;
            int r = f >> 4, c8 = (f & 15) << 3;
            cp16(smem_u32(bs + r * G_BLD + c8),
                 B + (size_t)(k0 + r) * N + n0 + c8);
        }
        cp_commit();
    };

    issue_stage(0);
    issue_stage(1);

    for (int it = 0; it < iters; ++it) {
        cp_wait<1>();
        __syncthreads();

        if (it + 2 < iters) issue_stage(it + 2);
        else                cp_commit();

        const int s = it % G_STG;
        const uint32_t a_base = smb + (s * G_ASZ
                              + (wmi * 32 + a_row) * G_ALD + a_col) * 2;
        const uint32_t b_base = smb + (G_STG * G_ASZ + s * G_BSZ
                              + b_row * G_BLD + wni * 64 + b_col) * 2;

#pragma unroll
        for (int ks = 0; ks < 4; ++ks) {
            uint32_t af[2][4];
#pragma unroll
            for (int mi = 0; mi < 2; ++mi)
                ldsm4(af[mi][0], af[mi][1], af[mi][2], af[mi][3],
                      a_base + (mi * 16 * G_ALD + ks * 16) * 2);
            uint32_t bf[4][4];
#pragma unroll
            for (int p = 0; p < 4; ++p)
                ldsm4t(bf[p][0], bf[p][1], bf[p][2], bf[p][3],
                       b_base + (ks * 16 * G_BLD + p * 16) * 2);
#pragma unroll
            for (int mi = 0; mi < 2; ++mi)
#pragma unroll
                for (int p = 0; p < 4; ++p) {
                    mma16816(cfr[mi][2 * p],     af[mi], bf[p][0], bf[p][1]);
                    mma16816(cfr[mi][2 * p + 1], af[mi], bf[p][2], bf[p][3]);
                }
        }
    }

    // ---- Epilogue: bias (+ Q_SCALE for the Q buffer) + store ----
    const int nc = n0 & 1023;
    const int colw = wni * 64 + 2 * (lane & 3);
    float2 bv[8];
#pragma unroll
    for (int nt = 0; nt < 8; ++nt) {
        bv[nt].x = bias[n0 + colw + nt * 8];
        bv[nt].y = bias[n0 + colw + nt * 8 + 1];
    }
    const int row0 = m0 + wmi * 32 + (lane >> 2);

    if (ROUND_OUT) {
        __half* outp = (n0 < 1024) ? (__half*)out0v
                     : ((n0 < 2048) ? (__half*)out1v : (__half*)out2v);
        const float osc = (n0 < 1024) ? Q_SCALE : 1.0f;   // Q pre-scaled (log2 domain)
#pragma unroll
        for (int mi = 0; mi < 2; ++mi) {
#pragma unroll
            for (int nt = 0; nt < 8; ++nt) {
                int col = nc + colw + nt * 8;
                __half2 v0 = __floats2half2_rn((cfr[mi][nt][0] + bv[nt].x) * osc,
                                               (cfr[mi][nt][1] + bv[nt].y) * osc);
                __half2 v1 = __floats2half2_rn((cfr[mi][nt][2] + bv[nt].x) * osc,
                                               (cfr[mi][nt][3] + bv[nt].y) * osc);
                *(__half2*)(outp + (size_t)(row0 + mi * 16) * 1024 + col) = v0;
                *(__half2*)(outp + (size_t)(row0 + mi * 16 + 8) * 1024 + col) = v1;
            }
        }
    } else {
        float* outp = (n0 < 1024) ? (float*)out0v
                    : ((n0 < 2048) ? (float*)out1v : (float*)out2v);
#pragma unroll
        for (int mi = 0; mi < 2; ++mi) {
#pragma unroll
            for (int nt = 0; nt < 8; ++nt) {
                int col = nc + colw + nt * 8;
                float2 v0 = { cfr[mi][nt][0] + bv[nt].x, cfr[mi][nt][1] + bv[nt].y };
                float2 v1 = { cfr[mi][nt][2] + bv[nt].x, cfr[mi][nt][3] + bv[nt].y };
                *(float2*)(outp + (size_t)(row0 + mi * 16) * 1024 + col) = v0;
                *(float2*)(outp + (size_t)(row0 + mi * 16 + 8) * 1024 + col) = v1;
            }
        }
    }
}

// ---------------------------------------------------------------------------
// Flash attention (causal), FA2-style. Br=128, Bc=64, hd=64, 256 thr.
// NOW pinned to 2 CTAs/SM (regs<=128). S is in log2 domain (Q pre-scaled by
// 0.125*log2e); softmax uses exp2f.
// ---------------------------------------------------------------------------
#define FLD 72
#define FQ_OFF  0
#define FK_OFF  18432
#define FV_OFF  (18432 + 27648)
#define F_SMEM  (18432 + 2 * 27648)  // 73728

__global__ __launch_bounds__(256, 2) void flash_fa2_kernel(
    const __half* __restrict__ Qg, const __half* __restrict__ Kg,
    const __half* __restrict__ Vg, __half* __restrict__ yt)
{
    extern __shared__ char smc[];
    const uint32_t smb = smem_u32(smc);
    const uint32_t kbA[3] = { smb + FK_OFF, smb + FK_OFF + 9216, smb + FK_OFF + 18432 };
    const uint32_t vbA[3] = { smb + FV_OFF, smb + FV_OFF + 9216, smb + FV_OFF + 18432 };

    const int qt   = gridDim.x - 1 - blockIdx.x;
    const int bh   = blockIdx.y;
    const int tid  = threadIdx.x;
    const int w    = tid >> 5;
    const int lane = tid & 31;

    const int q_row = (lane & 15);
    const int q_col = (lane >> 4) << 3;
    const int k_row = (lane & 7) + ((lane >> 4) << 3);
    const int k_col = ((lane >> 3) & 1) << 3;
    const int v_row = (lane & 7) + (((lane >> 3) & 1) << 3);
    const int v_col = (lane >> 4) << 3;

    const size_t head_off = (size_t)bh * 131072u;
    const __half* qg = Qg + head_off + (size_t)qt * 8192u;
    const __half* kg = Kg + head_off;
    const __half* vg = Vg + head_off;

#pragma unroll
    for (int t = 0; t < 4; ++t) {
        int f = tid + t * 256;
        int rr = f >> 3, c8 = (f & 7) << 3;
        cp16(smb + FQ_OFF + (rr * FLD + c8) * 2, qg + rr * 64 + c8);
    }
    cp_commit();

    auto issue_kv = [&](int kt) {
        const int buf = kt % 3;
        const __half* kp = kg + (size_t)kt * 4096u;
        const __half* vp = vg + (size_t)kt * 4096u;
#pragma unroll
        for (int t = 0; t < 2; ++t) {
            int f = tid + t * 256;
            int rr = f >> 3, c8 = (f & 7) << 3;
            cp16(kbA[buf] + (rr * FLD + c8) * 2, kp + rr * 64 + c8);
            cp16(vbA[buf] + (rr * FLD + c8) * 2, vp + rr * 64 + c8);
        }
        cp_commit();
    };

    const int n_kt = 2 * (qt + 1);
    issue_kv(0);
    issue_kv(1);

    cp_wait<2>();
    __syncthreads();

    uint32_t qf[4][4];
#pragma unroll
    for (int kk = 0; kk < 4; ++kk) {
        uint32_t a = smb + FQ_OFF
                   + ((w * 16 + q_row) * FLD + kk * 16 + q_col) * 2;
        ldsm4(qf[kk][0], qf[kk][1], qf[kk][2], qf[kk][3], a);
    }

    float oacc[8][4];
#pragma unroll
    for (int nt = 0; nt < 8; ++nt)
#pragma unroll
        for (int j = 0; j < 4; ++j) oacc[nt][j] = 0.0f;
    float m_lo = -1e30f, m_hi = -1e30f;
    float l_lo = 0.0f,   l_hi = 0.0f;

    const int row_g_lo = qt * 128 + w * 16 + (lane >> 2);
    const int row_g_hi = row_g_lo + 8;

    for (int kt = 0; kt < n_kt; ++kt) {
        const int buf = kt % 3;
        cp_wait<1>();
        __syncthreads();
        if (kt + 2 < n_kt) issue_kv(kt + 2);
        else               cp_commit();

        float sacc[8][4];
#pragma unroll
        for (int nt = 0; nt < 8; ++nt)
#pragma unroll
            for (int j = 0; j < 4; ++j) sacc[nt][j] = 0.0f;
#pragma unroll
        for (int p = 0; p < 4; ++p) {
#pragma unroll
            for (int kk = 0; kk < 4; ++kk) {
                uint32_t b0, b1, b2, b3;
                uint32_t a = kbA[buf]
                           + ((p * 16 + k_row) * FLD + kk * 16 + k_col) * 2;
                ldsm4(b0, b1, b2, b3, a);
                mma16816(sacc[2 * p],     qf[kk], b0, b1);
                mma16816(sacc[2 * p + 1], qf[kk], b2, b3);
            }
        }

        if (kt >= 2 * qt) {
            const int cb = kt * 64 + 2 * (lane & 3);
#pragma unroll
            for (int nt = 0; nt < 8; ++nt) {
                int c = cb + nt * 8;
                if (c     > row_g_lo) sacc[nt][0] = -1e30f;
                if (c + 1 > row_g_lo) sacc[nt][1] = -1e30f;
                if (c     > row_g_hi) sacc[nt][2] = -1e30f;
                if (c + 1 > row_g_hi) sacc[nt][3] = -1e30f;
            }
        }

        float mx_lo = -1e30f, mx_hi = -1e30f;
#pragma unroll
        for (int nt = 0; nt < 8; ++nt) {
            mx_lo = fmaxf(mx_lo, fmaxf(sacc[nt][0], sacc[nt][1]));
            mx_hi = fmaxf(mx_hi, fmaxf(sacc[nt][2], sacc[nt][3]));
        }
        mx_lo = fmaxf(mx_lo, __shfl_xor_sync(0xffffffffu, mx_lo, 1));
        mx_lo = fmaxf(mx_lo, __shfl_xor_sync(0xffffffffu, mx_lo, 2));
        mx_hi = fmaxf(mx_hi, __shfl_xor_sync(0xffffffffu, mx_hi, 1));
        mx_hi = fmaxf(mx_hi, __shfl_xor_sync(0xffffffffu, mx_hi, 2));

        const float mn_lo = fmaxf(m_lo, mx_lo);
        const float mn_hi = fmaxf(m_hi, mx_hi);
        const float al_lo = exp2f(m_lo - mn_lo);
        const float al_hi = exp2f(m_hi - mn_hi);
        m_lo = mn_lo; m_hi = mn_hi;

        float sum_lo = 0.0f, sum_hi = 0.0f;
        uint32_t pfr[4][4];
#pragma unroll
        for (int nt = 0; nt < 8; ++nt) {
            float p0 = exp2f(sacc[nt][0] - mn_lo);
            float p1 = exp2f(sacc[nt][1] - mn_lo);
            float p2 = exp2f(sacc[nt][2] - mn_hi);
            float p3 = exp2f(sacc[nt][3] - mn_hi);
            sum_lo += p0 + p1;
            sum_hi += p2 + p3;
            __half2 h01 = __floats2half2_rn(p0, p1);
            __half2 h23 = __floats2half2_rn(p2, p3);
            pfr[nt >> 1][(nt & 1) * 2 + 0] = *(uint32_t*)&h01;
            pfr[nt >> 1][(nt & 1) * 2 + 1] = *(uint32_t*)&h23;
        }
        l_lo = l_lo * al_lo + sum_lo;
        l_hi = l_hi * al_hi + sum_hi;

#pragma unroll
        for (int nt = 0; nt < 8; ++nt) {
            oacc[nt][0] *= al_lo; oacc[nt][1] *= al_lo;
            oacc[nt][2] *= al_hi; oacc[nt][3] *= al_hi;
        }

#pragma unroll
        for (int p = 0; p < 4; ++p) {
#pragma unroll
            for (int t = 0; t < 4; ++t) {
                uint32_t b0, b1, b2, b3;
                uint32_t a = vbA[buf]
                           + ((t * 16 + v_row) * FLD + p * 16 + v_col) * 2;
                ldsm4t(b0, b1, b2, b3, a);
                mma16816(oacc[2 * p],     pfr[t], b0, b1);
                mma16816(oacc[2 * p + 1], pfr[t], b2, b3);
            }
        }
    }

    l_lo += __shfl_xor_sync(0xffffffffu, l_lo, 1);
    l_lo += __shfl_xor_sync(0xffffffffu, l_lo, 2);
    l_hi += __shfl_xor_sync(0xffffffffu, l_hi, 1);
    l_hi += __shfl_xor_sync(0xffffffffu, l_hi, 2);
    const float inv_lo = 1.0f / l_lo;
    const float inv_hi = 1.0f / l_hi;

    const int b = bh >> 4;
    const int h = bh & 15;
    const int tq_lo = qt * 128 + w * 16 + (lane >> 2);
    __half* dst_lo = yt + ((size_t)(b * 2048 + tq_lo)) * 1024u + h * 64 + 2 * (lane & 3);
    __half* dst_hi = dst_lo + 8u * 1024u;
#pragma unroll
    for (int nt = 0; nt < 8; ++nt) {
        __half2 vlo = __floats2half2_rn(oacc[nt][0] * inv_lo, oacc[nt][1] * inv_lo);
        __half2 vhi = __floats2half2_rn(oacc[nt][2] * inv_hi, oacc[nt][3] * inv_hi);
        *(__half2*)(dst_lo + nt * 8) = vlo;
        *(__half2*)(dst_hi + nt * 8) = vhi;
    }
}

// ---------------------------------------------------------------------------
// Launch
// ---------------------------------------------------------------------------
extern "C" void kernel_launch(void* const* d_in, const int* in_sizes, int n_in,
                              void* d_out, int out_size)
{
    const float* x     = (const float*)d_in[0];
    const float* Wqkv  = (const float*)d_in[1];
    const float* bqkv  = (const float*)d_in[2];
    const float* Wproj = (const float*)d_in[3];
    const float* bproj = (const float*)d_in[4];
    float* out = (float*)d_out;

    __half *q, *k, *v, *yt, *xh, *wqkvh, *wprojh;
    cudaGetSymbolAddress((void**)&q,  g_q);
    cudaGetSymbolAddress((void**)&k,  g_k);
    cudaGetSymbolAddress((void**)&v,  g_v);
    cudaGetSymbolAddress((void**)&yt, g_yt);
    cudaGetSymbolAddress((void**)&xh, g_xh);
    cudaGetSymbolAddress((void**)&wqkvh, g_wqkvh);
    cudaGetSymbolAddress((void**)&wprojh, g_wprojh);

    const int M = 4096, C = 1024;

    // 0) fp32 -> fp16 conversion (single launch)
    {
        uint32_t total = N8_X + N8_WQ + N8_WP;
        to_half3_kernel<<<(total + 255) / 256, 256>>>(x, Wqkv, Wproj,
                                                      xh, wqkvh, wprojh);
    }

    cudaFuncSetAttribute(gemm_mma_kernel<1>,
                         cudaFuncAttributeMaxDynamicSharedMemorySize, G_SMEM_BYTES);
    cudaFuncSetAttribute(gemm_mma_kernel<0>,
                         cudaFuncAttributeMaxDynamicSharedMemorySize, G_SMEM_BYTES);

    // 1) QKV projection -> half q/k/v (Q pre-scaled by 0.125*log2e)
    {
        dim3 grid(3 * C / 128, M / 128);   // (24, 32)
        gemm_mma_kernel<1><<<grid, 256, G_SMEM_BYTES>>>(xh, wqkvh, bqkv,
                                                        q, k, v, M, 3 * C, C);
    }

    // 2) Flash attention (causal) -> yt (half), 2 CTAs/SM
    {
        cudaFuncSetAttribute(flash_fa2_kernel,
                             cudaFuncAttributeMaxDynamicSharedMemorySize, F_SMEM);
        dim3 grid(2048 / 128, 32);         // (16, 32)
        flash_fa2_kernel<<<grid, 256, F_SMEM>>>(q, k, v, yt);
    }

    // 3) Output projection -> fp32 out
    {
        dim3 grid(C / 128, M / 128);       // (8, 32)
        gemm_mma_kernel<0><<<grid, 256, G_SMEM_BYTES>>>(yt, wprojh, bproj,
                                                        out, out, out, M, C, C);
    }
}

// round 15
// speedup vs baseline: 1.0492x; 1.0022x over previous
#include <cuda_runtime.h>
#include <cuda_fp16.h>
#include <cstdint>

// ---------------------------------------------------------------------------
// Scratch (device globals)
// ---------------------------------------------------------------------------
__device__ __half g_q [2u * 2048u * 1024u];
__device__ __half g_k [2u * 2048u * 1024u];
__device__ __half g_v [2u * 2048u * 1024u];
__device__ __half g_yt[2u * 2048u * 1024u];
__device__ __half g_xh   [4096u * 1024u];
__device__ __half g_wqkvh[1024u * 3072u];
__device__ __half g_wprojh[1024u * 1024u];

// ---------------------------------------------------------------------------
// cp.async helpers
// ---------------------------------------------------------------------------
__device__ __forceinline__ uint32_t smem_u32(const void* p) {
    return (uint32_t)__cvta_generic_to_shared(p);
}
__device__ __forceinline__ void cp16(uint32_t dst, const void* src) {
    asm volatile("cp.async.cg.shared.global [%0], [%1], 16;"
                 :: "r"(dst), "l"(src) : "memory");
}
__device__ __forceinline__ void cp_commit() {
    asm volatile("cp.async.commit_group;" ::: "memory");
}
template <int N>
__device__ __forceinline__ void cp_wait() {
    asm volatile("cp.async.wait_group %0;" :: "n"(N) : "memory");
}

// ---------------------------------------------------------------------------
// mma / ldmatrix helpers
// ---------------------------------------------------------------------------
__device__ __forceinline__ void mma16816(float* c, const uint32_t* a,
                                         uint32_t b0, uint32_t b1) {
    asm volatile(
        "mma.sync.aligned.m16n8k16.row.col.f32.f16.f16.f32 "
        "{%0,%1,%2,%3}, {%4,%5,%6,%7}, {%8,%9}, {%0,%1,%2,%3};"
        : "+f"(c[0]), "+f"(c[1]), "+f"(c[2]), "+f"(c[3])
        : "r"(a[0]), "r"(a[1]), "r"(a[2]), "r"(a[3]), "r"(b0), "r"(b1));
}
__device__ __forceinline__ void ldsm4(uint32_t& r0, uint32_t& r1,
                                      uint32_t& r2, uint32_t& r3, uint32_t a) {
    asm volatile("ldmatrix.sync.aligned.m8n8.x4.shared.b16 {%0,%1,%2,%3}, [%4];"
                 : "=r"(r0), "=r"(r1), "=r"(r2), "=r"(r3) : "r"(a));
}
__device__ __forceinline__ void ldsm4t(uint32_t& r0, uint32_t& r1,
                                       uint32_t& r2, uint32_t& r3, uint32_t a) {
    asm volatile("ldmatrix.sync.aligned.m8n8.x4.trans.shared.b16 {%0,%1,%2,%3}, [%4];"
                 : "=r"(r0), "=r"(r1), "=r"(r2), "=r"(r3) : "r"(a));
}

// ---------------------------------------------------------------------------
// Combined fp32 -> fp16 conversion, grid-stride (16 elems/thread/step)
// ---------------------------------------------------------------------------
#define N8_X  (4096u * 1024u / 8u)
#define N8_WQ (1024u * 3072u / 8u)
#define N8_WP (1024u * 1024u / 8u)
#define N8_TOT (N8_X + N8_WQ + N8_WP)

__global__ void to_half3_kernel(const float* __restrict__ x,
                                const float* __restrict__ wq,
                                const float* __restrict__ wp,
                                __half* __restrict__ xh,
                                __half* __restrict__ wqh,
                                __half* __restrict__ wph)
{
    for (uint32_t i = blockIdx.x * blockDim.x + threadIdx.x; i < N8_TOT;
         i += gridDim.x * blockDim.x) {
        const float* in;
        __half* out;
        uint32_t j;
        if (i < N8_X)              { in = x;  out = xh;  j = i; }
        else if (i < N8_X + N8_WQ) { in = wq; out = wqh; j = i - N8_X; }
        else                       { in = wp; out = wph; j = i - N8_X - N8_WQ; }
        float4 a = ((const float4*)in)[j * 2];
        float4 b = ((const float4*)in)[j * 2 + 1];
        __half h[8];
        h[0] = __float2half_rn(a.x); h[1] = __float2half_rn(a.y);
        h[2] = __float2half_rn(a.z); h[3] = __float2half_rn(a.w);
        h[4] = __float2half_rn(b.x); h[5] = __float2half_rn(b.y);
        h[6] = __float2half_rn(b.z); h[7] = __float2half_rn(b.w);
        ((uint4*)out)[j] = *(uint4*)h;
    }
}

// ---------------------------------------------------------------------------
// FP16 raw-mma GEMM (fp32 accumulate), BK=64, 3-stage cp.async, 2 CTAs/SM.
// Issue-before-wait: sync -> issue(it+2) -> cp_wait<2> -> compute.
// Q output scaled by 0.125*log2(e) so flash can use exp2.
// ---------------------------------------------------------------------------
#define G_ALD 72
#define G_BLD 136
#define G_ASZ (128 * G_ALD)
#define G_BSZ (64 * G_BLD)
#define G_STG 3
#define G_SMEM_BYTES (G_STG * (G_ASZ + G_BSZ) * 2)   // 107520

#define Q_SCALE (0.125f * 1.44269504088896340736f)

template <int ROUND_OUT>
__global__ __launch_bounds__(256, 2) void gemm_mma_kernel(
    const __half* __restrict__ A, const __half* __restrict__ B,
    const float* __restrict__ bias,
    void* __restrict__ out0v, void* __restrict__ out1v, void* __restrict__ out2v,
    int M, int N, int K)
{
    extern __shared__ char gsmc[];
    __half* gsm = (__half*)gsmc;
    const uint32_t smb = smem_u32(gsmc);

    const int tid  = threadIdx.x;
    const int wid  = tid >> 5;
    const int lane = tid & 31;
    const int wmi  = wid & 3;
    const int wni  = wid >> 2;
    const int m0   = blockIdx.y * 128;
    const int n0   = blockIdx.x * 128;

    const int a_row = (lane & 15);
    const int a_col = (lane >> 4) << 3;
    const int b_row = (lane & 7) + (((lane >> 3) & 1) << 3);
    const int b_col = (lane >> 4) << 3;

    float cfr[2][8][4];
#pragma unroll
    for (int mi = 0; mi < 2; ++mi)
#pragma unroll
        for (int nt = 0; nt < 8; ++nt)
#pragma unroll
            for (int j = 0; j < 4; ++j) cfr[mi][nt][j] = 0.0f;

    const int iters = K >> 6;

    auto issue_stage = [&](int stage) {
        const int s = stage % G_STG;
        const int k0 = stage << 6;
        __half* as = gsm + s * G_ASZ;
        __half* bs = gsm + G_STG * G_ASZ + s * G_BSZ;
#pragma unroll
        for (int t = 0; t < 4; ++t) {
            int f = tid + t * 256;
            int r = f >> 3, c8 = (f & 7) << 3;
            cp16(smem_u32(as + r * G_ALD + c8),
                 A + (size_t)(m0 + r) * K + k0 + c8);
        }
#pragma unroll
        for (int t = 0; t < 4; ++t) {
            int f = tid + t * 256;
            int r = f >> 4, c8 = (f & 15) << 3;
            cp16(smem_u32(bs + r * G_BLD + c8),
                 B + (size_t)(k0 + r) * N + n0 + c8);
        }
        cp_commit();
    };

    issue_stage(0);
    issue_stage(1);
    // first iteration: nothing written yet into stage-2 buffer, so it can be
    // issued before any wait.
    if (2 < iters) issue_stage(2);
    else           cp_commit();

    for (int it = 0; it < iters; ++it) {
        cp_wait<2>();          // stage `it` resident (2 newer groups allowed)
        __syncthreads();       // all warps seen it; reads of stage it-1 done

        const int s = it % G_STG;
        const uint32_t a_base = smb + (s * G_ASZ
                              + (wmi * 32 + a_row) * G_ALD + a_col) * 2;
        const uint32_t b_base = smb + (G_STG * G_ASZ + s * G_BSZ
                              + b_row * G_BLD + wni * 64 + b_col) * 2;

#pragma unroll
        for (int ks = 0; ks < 4; ++ks) {
            uint32_t af[2][4];
#pragma unroll
            for (int mi = 0; mi < 2; ++mi)
                ldsm4(af[mi][0], af[mi][1], af[mi][2], af[mi][3],
                      a_base + (mi * 16 * G_ALD + ks * 16) * 2);
            uint32_t bf[4][4];
#pragma unroll
            for (int p = 0; p < 4; ++p)
                ldsm4t(bf[p][0], bf[p][1], bf[p][2], bf[p][3],
                       b_base + (ks * 16 * G_BLD + p * 16) * 2);
#pragma unroll
            for (int mi = 0; mi < 2; ++mi)
#pragma unroll
                for (int p = 0; p < 4; ++p) {
                    mma16816(cfr[mi][2 * p],     af[mi], bf[p][0], bf[p][1]);
                    mma16816(cfr[mi][2 * p + 1], af[mi], bf[p][2], bf[p][3]);
                }
        }
        __syncthreads();       // compute done; stage (it+3)%3 == s free to refill

        if (it + 3 < iters) issue_stage(it + 3);
        else                cp_commit();
    }

    // ---- Epilogue: bias (+ Q_SCALE for the Q buffer) + store ----
    const int nc = n0 & 1023;
    const int colw = wni * 64 + 2 * (lane & 3);
    float2 bv[8];
#pragma unroll
    for (int nt = 0; nt < 8; ++nt) {
        bv[nt].x = bias[n0 + colw + nt * 8];
        bv[nt].y = bias[n0 + colw + nt * 8 + 1];
    }
    const int row0 = m0 + wmi * 32 + (lane >> 2);

    if (ROUND_OUT) {
        __half* outp = (n0 < 1024) ? (__half*)out0v
                     : ((n0 < 2048) ? (__half*)out1v : (__half*)out2v);
        const float osc = (n0 < 1024) ? Q_SCALE : 1.0f;
#pragma unroll
        for (int mi = 0; mi < 2; ++mi) {
#pragma unroll
            for (int nt = 0; nt < 8; ++nt) {
                int col = nc + colw + nt * 8;
                __half2 v0 = __floats2half2_rn((cfr[mi][nt][0] + bv[nt].x) * osc,
                                               (cfr[mi][nt][1] + bv[nt].y) * osc);
                __half2 v1 = __floats2half2_rn((cfr[mi][nt][2] + bv[nt].x) * osc,
                                               (cfr[mi][nt][3] + bv[nt].y) * osc);
                *(__half2*)(outp + (size_t)(row0 + mi * 16) * 1024 + col) = v0;
                *(__half2*)(outp + (size_t)(row0 + mi * 16 + 8) * 1024 + col) = v1;
            }
        }
    } else {
        float* outp = (n0 < 1024) ? (float*)out0v
                    : ((n0 < 2048) ? (float*)out1v : (float*)out2v);
#pragma unroll
        for (int mi = 0; mi < 2; ++mi) {
#pragma unroll
            for (int nt = 0; nt < 8; ++nt) {
                int col = nc + colw + nt * 8;
                float2 v0 = { cfr[mi][nt][0] + bv[nt].x, cfr[mi][nt][1] + bv[nt].y };
                float2 v1 = { cfr[mi][nt][2] + bv[nt].x, cfr[mi][nt][3] + bv[nt].y };
                *(float2*)(outp + (size_t)(row0 + mi * 16) * 1024 + col) = v0;
                *(float2*)(outp + (size_t)(row0 + mi * 16 + 8) * 1024 + col) = v1;
            }
        }
    }
}

// ---------------------------------------------------------------------------
// Flash attention (causal), FA2-style. Br=128, Bc=64, hd=64, 256 thr,
// 2 CTAs/SM, exp2-domain softmax, 3-deep K/V pipeline with issue-before-wait.
// ---------------------------------------------------------------------------
#define FLD 72
#define FQ_OFF  0
#define FK_OFF  18432
#define FV_OFF  (18432 + 27648)
#define F_SMEM  (18432 + 2 * 27648)  // 73728

__global__ __launch_bounds__(256, 2) void flash_fa2_kernel(
    const __half* __restrict__ Qg, const __half* __restrict__ Kg,
    const __half* __restrict__ Vg, __half* __restrict__ yt)
{
    extern __shared__ char smc[];
    const uint32_t smb = smem_u32(smc);
    const uint32_t kbA[3] = { smb + FK_OFF, smb + FK_OFF + 9216, smb + FK_OFF + 18432 };
    const uint32_t vbA[3] = { smb + FV_OFF, smb + FV_OFF + 9216, smb + FV_OFF + 18432 };

    const int qt   = gridDim.x - 1 - blockIdx.x;
    const int bh   = blockIdx.y;
    const int tid  = threadIdx.x;
    const int w    = tid >> 5;
    const int lane = tid & 31;

    const int q_row = (lane & 15);
    const int q_col = (lane >> 4) << 3;
    const int k_row = (lane & 7) + ((lane >> 4) << 3);
    const int k_col = ((lane >> 3) & 1) << 3;
    const int v_row = (lane & 7) + (((lane >> 3) & 1) << 3);
    const int v_col = (lane >> 4) << 3;

    const size_t head_off = (size_t)bh * 131072u;
    const __half* qg = Qg + head_off + (size_t)qt * 8192u;
    const __half* kg = Kg + head_off;
    const __half* vg = Vg + head_off;

#pragma unroll
    for (int t = 0; t < 4; ++t) {
        int f = tid + t * 256;
        int rr = f >> 3, c8 = (f & 7) << 3;
        cp16(smb + FQ_OFF + (rr * FLD + c8) * 2, qg + rr * 64 + c8);
    }
    cp_commit();

    auto issue_kv = [&](int kt) {
        const int buf = kt % 3;
        const __half* kp = kg + (size_t)kt * 4096u;
        const __half* vp = vg + (size_t)kt * 4096u;
#pragma unroll
        for (int t = 0; t < 2; ++t) {
            int f = tid + t * 256;
            int rr = f >> 3, c8 = (f & 7) << 3;
            cp16(kbA[buf] + (rr * FLD + c8) * 2, kp + rr * 64 + c8);
            cp16(vbA[buf] + (rr * FLD + c8) * 2, vp + rr * 64 + c8);
        }
        cp_commit();
    };

    const int n_kt = 2 * (qt + 1);
    issue_kv(0);
    issue_kv(1);
    if (2 < n_kt) issue_kv(2);   // 3rd buffer free at start — issue early
    else          cp_commit();

    cp_wait<3>();                // Q resident (3 KV groups may be in flight)
    __syncthreads();

    uint32_t qf[4][4];
#pragma unroll
    for (int kk = 0; kk < 4; ++kk) {
        uint32_t a = smb + FQ_OFF
                   + ((w * 16 + q_row) * FLD + kk * 16 + q_col) * 2;
        ldsm4(qf[kk][0], qf[kk][1], qf[kk][2], qf[kk][3], a);
    }

    float oacc[8][4];
#pragma unroll
    for (int nt = 0; nt < 8; ++nt)
#pragma unroll
        for (int j = 0; j < 4; ++j) oacc[nt][j] = 0.0f;
    float m_lo = -1e30f, m_hi = -1e30f;
    float l_lo = 0.0f,   l_hi = 0.0f;

    const int row_g_lo = qt * 128 + w * 16 + (lane >> 2);
    const int row_g_hi = row_g_lo + 8;

    for (int kt = 0; kt < n_kt; ++kt) {
        const int buf = kt % 3;
        cp_wait<2>();            // KV(kt) resident (kt+1, kt+2 may be in flight)
        __syncthreads();

        float sacc[8][4];
#pragma unroll
        for (int nt = 0; nt < 8; ++nt)
#pragma unroll
            for (int j = 0; j < 4; ++j) sacc[nt][j] = 0.0f;
#pragma unroll
        for (int p = 0; p < 4; ++p) {
#pragma unroll
            for (int kk = 0; kk < 4; ++kk) {
                uint32_t b0, b1, b2, b3;
                uint32_t a = kbA[buf]
                           + ((p * 16 + k_row) * FLD + kk * 16 + k_col) * 2;
                ldsm4(b0, b1, b2, b3, a);
                mma16816(sacc[2 * p],     qf[kk], b0, b1);
                mma16816(sacc[2 * p + 1], qf[kk], b2, b3);
            }
        }

        if (kt >= 2 * qt) {
            const int cb = kt * 64 + 2 * (lane & 3);
#pragma unroll
            for (int nt = 0; nt < 8; ++nt) {
                int c = cb + nt * 8;
                if (c     > row_g_lo) sacc[nt][0] = -1e30f;
                if (c + 1 > row_g_lo) sacc[nt][1] = -1e30f;
                if (c     > row_g_hi) sacc[nt][2] = -1e30f;
                if (c + 1 > row_g_hi) sacc[nt][3] = -1e30f;
            }
        }

        float mx_lo = -1e30f, mx_hi = -1e30f;
#pragma unroll
        for (int nt = 0; nt < 8; ++nt) {
            mx_lo = fmaxf(mx_lo, fmaxf(sacc[nt][0], sacc[nt][1]));
            mx_hi = fmaxf(mx_hi, fmaxf(sacc[nt][2], sacc[nt][3]));
        }
        mx_lo = fmaxf(mx_lo, __shfl_xor_sync(0xffffffffu, mx_lo, 1));
        mx_lo = fmaxf(mx_lo, __shfl_xor_sync(0xffffffffu, mx_lo, 2));
        mx_hi = fmaxf(mx_hi, __shfl_xor_sync(0xffffffffu, mx_hi, 1));
        mx_hi = fmaxf(mx_hi, __shfl_xor_sync(0xffffffffu, mx_hi, 2));

        const float mn_lo = fmaxf(m_lo, mx_lo);
        const float mn_hi = fmaxf(m_hi, mx_hi);
        const float al_lo = exp2f(m_lo - mn_lo);
        const float al_hi = exp2f(m_hi - mn_hi);
        m_lo = mn_lo; m_hi = mn_hi;

        float sum_lo = 0.0f, sum_hi = 0.0f;
        uint32_t pfr[4][4];
#pragma unroll
        for (int nt = 0; nt < 8; ++nt) {
            float p0 = exp2f(sacc[nt][0] - mn_lo);
            float p1 = exp2f(sacc[nt][1] - mn_lo);
            float p2 = exp2f(sacc[nt][2] - mn_hi);
            float p3 = exp2f(sacc[nt][3] - mn_hi);
            sum_lo += p0 + p1;
            sum_hi += p2 + p3;
            __half2 h01 = __floats2half2_rn(p0, p1);
            __half2 h23 = __floats2half2_rn(p2, p3);
            pfr[nt >> 1][(nt & 1) * 2 + 0] = *(uint32_t*)&h01;
            pfr[nt >> 1][(nt & 1) * 2 + 1] = *(uint32_t*)&h23;
        }
        l_lo = l_lo * al_lo + sum_lo;
        l_hi = l_hi * al_hi + sum_hi;

#pragma unroll
        for (int nt = 0; nt < 8; ++nt) {
            oacc[nt][0] *= al_lo; oacc[nt][1] *= al_lo;
            oacc[nt][2] *= al_hi; oacc[nt][3] *= al_hi;
        }

#pragma unroll
        for (int p = 0; p < 4; ++p) {
#pragma unroll
            for (int t = 0; t < 4; ++t) {
                uint32_t b0, b1, b2, b3;
                uint32_t a = vbA[buf]
                           + ((t * 16 + v_row) * FLD + p * 16 + v_col) * 2;
                ldsm4t(b0, b1, b2, b3, a);
                mma16816(oacc[2 * p],     pfr[t], b0, b1);
                mma16816(oacc[2 * p + 1], pfr[t], b2, b3);
            }
        }

        __syncthreads();        // all reads of buf done -> safe to refill
        if (kt + 3 < n_kt) issue_kv(kt + 3);
        else               cp_commit();
    }

    l_lo += __shfl_xor_sync(0xffffffffu, l_lo, 1);
    l_lo += __shfl_xor_sync(0xffffffffu, l_lo, 2);
    l_hi += __shfl_xor_sync(0xffffffffu, l_hi, 1);
    l_hi += __shfl_xor_sync(0xffffffffu, l_hi, 2);
    const float inv_lo = 1.0f / l_lo;
    const float inv_hi = 1.0f / l_hi;

    const int b = bh >> 4;
    const int h = bh & 15;
    const int tq_lo = qt * 128 + w * 16 + (lane >> 2);
    __half* dst_lo = yt + ((size_t)(b * 2048 + tq_lo)) * 1024u + h * 64 + 2 * (lane & 3);
    __half* dst_hi = dst_lo + 8u * 1024u;
#pragma unroll
    for (int nt = 0; nt < 8; ++nt) {
        __half2 vlo = __floats2half2_rn(oacc[nt][0] * inv_lo, oacc[nt][1] * inv_lo);
        __half2 vhi = __floats2half2_rn(oacc[nt][2] * inv_hi, oacc[nt][3] * inv_hi);
        *(__half2*)(dst_lo + nt * 8) = vlo;
        *(__half2*)(dst_hi + nt * 8) = vhi;
    }
}

// ---------------------------------------------------------------------------
// Launch
// ---------------------------------------------------------------------------
extern "C" void kernel_launch(void* const* d_in, const int* in_sizes, int n_in,
                              void* d_out, int out_size)
{
    const float* x     = (const float*)d_in[0];
    const float* Wqkv  = (const float*)d_in[1];
    const float* bqkv  = (const float*)d_in[2];
    const float* Wproj = (const float*)d_in[3];
    const float* bproj = (const float*)d_in[4];
    float* out = (float*)d_out;

    __half *q, *k, *v, *yt, *xh, *wqkvh, *wprojh;
    cudaGetSymbolAddress((void**)&q,  g_q);
    cudaGetSymbolAddress((void**)&k,  g_k);
    cudaGetSymbolAddress((void**)&v,  g_v);
    cudaGetSymbolAddress((void**)&yt, g_yt);
    cudaGetSymbolAddress((void**)&xh, g_xh);
    cudaGetSymbolAddress((void**)&wqkvh, g_wqkvh);
    cudaGetSymbolAddress((void**)&wprojh, g_wprojh);

    const int M = 4096, C = 1024;

    // 0) fp32 -> fp16 conversion (grid-stride, 2 items per thread)
    {
        to_half3_kernel<<<2048, 256>>>(x, Wqkv, Wproj, xh, wqkvh, wprojh);
    }

    cudaFuncSetAttribute(gemm_mma_kernel<1>,
                         cudaFuncAttributeMaxDynamicSharedMemorySize, G_SMEM_BYTES);
    cudaFuncSetAttribute(gemm_mma_kernel<0>,
                         cudaFuncAttributeMaxDynamicSharedMemorySize, G_SMEM_BYTES);

    // 1) QKV projection -> half q/k/v (Q pre-scaled by 0.125*log2e)
    {
        dim3 grid(3 * C / 128, M / 128);   // (24, 32)
        gemm_mma_kernel<1><<<grid, 256, G_SMEM_BYTES>>>(xh, wqkvh, bqkv,
                                                        q, k, v, M, 3 * C, C);
    }

    // 2) Flash attention (causal) -> yt (half), 2 CTAs/SM
    {
        cudaFuncSetAttribute(flash_fa2_kernel,
                             cudaFuncAttributeMaxDynamicSharedMemorySize, F_SMEM);
        dim3 grid(2048 / 128, 32);         // (16, 32)
        flash_fa2_kernel<<<grid, 256, F_SMEM>>>(q, k, v, yt);
    }

    // 3) Output projection -> fp32 out
    {
        dim3 grid(C / 128, M / 128);       // (8, 32)
        gemm_mma_kernel<0><<<grid, 256, G_SMEM_BYTES>>>(yt, wprojh, bproj,
                                                        out, out, out, M, C, C);
    }
}

// round 16
// speedup vs baseline: 1.1579x; 1.1036x over previous
#include <cuda_runtime.h>
#include <cuda_fp16.h>
#include <cstdint>

// ---------------------------------------------------------------------------
// Scratch (device globals)
// ---------------------------------------------------------------------------
__device__ __half g_q [2u * 2048u * 1024u];
__device__ __half g_k [2u * 2048u * 1024u];
__device__ __half g_v [2u * 2048u * 1024u];
__device__ __half g_yt[2u * 2048u * 1024u];
__device__ __half g_xh   [4096u * 1024u];
__device__ __half g_wqkvh[1024u * 3072u];
__device__ __half g_wprojh[1024u * 1024u];

// ---------------------------------------------------------------------------
// cp.async helpers
// ---------------------------------------------------------------------------
__device__ __forceinline__ uint32_t smem_u32(const void* p) {
    return (uint32_t)__cvta_generic_to_shared(p);
}
__device__ __forceinline__ void cp16(uint32_t dst, const void* src) {
    asm volatile("cp.async.cg.shared.global [%0], [%1], 16;"
                 :: "r"(dst), "l"(src) : "memory");
}
__device__ __forceinline__ void cp_commit() {
    asm volatile("cp.async.commit_group;" ::: "memory");
}
template <int N>
__device__ __forceinline__ void cp_wait() {
    asm volatile("cp.async.wait_group %0;" :: "n"(N) : "memory");
}

// ---------------------------------------------------------------------------
// mma / ldmatrix helpers
// ---------------------------------------------------------------------------
__device__ __forceinline__ void mma16816(float* c, const uint32_t* a,
                                         uint32_t b0, uint32_t b1) {
    asm volatile(
        "mma.sync.aligned.m16n8k16.row.col.f32.f16.f16.f32 "
        "{%0,%1,%2,%3}, {%4,%5,%6,%7}, {%8,%9}, {%0,%1,%2,%3};"
        : "+f"(c[0]), "+f"(c[1]), "+f"(c[2]), "+f"(c[3])
        : "r"(a[0]), "r"(a[1]), "r"(a[2]), "r"(a[3]), "r"(b0), "r"(b1));
}
__device__ __forceinline__ void ldsm4(uint32_t& r0, uint32_t& r1,
                                      uint32_t& r2, uint32_t& r3, uint32_t a) {
    asm volatile("ldmatrix.sync.aligned.m8n8.x4.shared.b16 {%0,%1,%2,%3}, [%4];"
                 : "=r"(r0), "=r"(r1), "=r"(r2), "=r"(r3) : "r"(a));
}
__device__ __forceinline__ void ldsm4t(uint32_t& r0, uint32_t& r1,
                                       uint32_t& r2, uint32_t& r3, uint32_t a) {
    asm volatile("ldmatrix.sync.aligned.m8n8.x4.trans.shared.b16 {%0,%1,%2,%3}, [%4];"
                 : "=r"(r0), "=r"(r1), "=r"(r2), "=r"(r3) : "r"(a));
}

// ---------------------------------------------------------------------------
// Combined fp32 -> fp16 conversion, grid-stride
// ---------------------------------------------------------------------------
#define N8_X  (4096u * 1024u / 8u)
#define N8_WQ (1024u * 3072u / 8u)
#define N8_WP (1024u * 1024u / 8u)
#define N8_TOT (N8_X + N8_WQ + N8_WP)

__global__ void to_half3_kernel(const float* __restrict__ x,
                                const float* __restrict__ wq,
                                const float* __restrict__ wp,
                                __half* __restrict__ xh,
                                __half* __restrict__ wqh,
                                __half* __restrict__ wph)
{
    for (uint32_t i = blockIdx.x * blockDim.x + threadIdx.x; i < N8_TOT;
         i += gridDim.x * blockDim.x) {
        const float* in;
        __half* out;
        uint32_t j;
        if (i < N8_X)              { in = x;  out = xh;  j = i; }
        else if (i < N8_X + N8_WQ) { in = wq; out = wqh; j = i - N8_X; }
        else                       { in = wp; out = wph; j = i - N8_X - N8_WQ; }
        float4 a = ((const float4*)in)[j * 2];
        float4 b = ((const float4*)in)[j * 2 + 1];
        __half h[8];
        h[0] = __float2half_rn(a.x); h[1] = __float2half_rn(a.y);
        h[2] = __float2half_rn(a.z); h[3] = __float2half_rn(a.w);
        h[4] = __float2half_rn(b.x); h[5] = __float2half_rn(b.y);
        h[6] = __float2half_rn(b.z); h[7] = __float2half_rn(b.w);
        ((uint4*)out)[j] = *(uint4*)h;
    }
}

// ---------------------------------------------------------------------------
// FP16 raw-mma GEMM (fp32 accumulate), BK=64, 3-stage cp.async, 2 CTAs/SM.
// (unchanged best-measured body). Q output scaled by 0.125*log2(e).
// ---------------------------------------------------------------------------
#define G_ALD 72
#define G_BLD 136
#define G_ASZ (128 * G_ALD)
#define G_BSZ (64 * G_BLD)
#define G_STG 3
#define G_SMEM_BYTES (G_STG * (G_ASZ + G_BSZ) * 2)   // 107520

#define Q_SCALE (0.125f * 1.44269504088896340736f)

template <int ROUND_OUT>
__global__ __launch_bounds__(256, 2) void gemm_mma_kernel(
    const __half* __restrict__ A, const __half* __restrict__ B,
    const float* __restrict__ bias,
    void* __restrict__ out0v, void* __restrict__ out1v, void* __restrict__ out2v,
    int M, int N, int K)
{
    extern __shared__ char gsmc[];
    __half* gsm = (__half*)gsmc;
    const uint32_t smb = smem_u32(gsmc);

    const int tid  = threadIdx.x;
    const int wid  = tid >> 5;
    const int lane = tid & 31;
    const int wmi  = wid & 3;
    const int wni  = wid >> 2;
    const int m0   = blockIdx.y * 128;
    const int n0   = blockIdx.x * 128;

    const int a_row = (lane & 15);
    const int a_col = (lane >> 4) << 3;
    const int b_row = (lane & 7) + (((lane >> 3) & 1) << 3);
    const int b_col = (lane >> 4) << 3;

    float cfr[2][8][4];
#pragma unroll
    for (int mi = 0; mi < 2; ++mi)
#pragma unroll
        for (int nt = 0; nt < 8; ++nt)
#pragma unroll
            for (int j = 0; j < 4; ++j) cfr[mi][nt][j] = 0.0f;

    const int iters = K >> 6;

    auto issue_stage = [&](int stage) {
        const int s = stage % G_STG;
        const int k0 = stage << 6;
        __half* as = gsm + s * G_ASZ;
        __half* bs = gsm + G_STG * G_ASZ + s * G_BSZ;
#pragma unroll
        for (int t = 0; t < 4; ++t) {
            int f = tid + t * 256;
            int r = f >> 3, c8 = (f & 7) << 3;
            cp16(smem_u32(as + r * G_ALD + c8),
                 A + (size_t)(m0 + r) * K + k0 + c8);
        }
#pragma unroll
        for (int t = 0; t < 4; ++t) {
            int f = tid + t * 256;
            int r = f >> 4, c8 = (f & 15) << 3;
            cp16(smem_u32(bs + r * G_BLD + c8),
                 B + (size_t)(k0 + r) * N + n0 + c8);
        }
        cp_commit();
    };

    issue_stage(0);
    issue_stage(1);
    if (2 < iters) issue_stage(2);
    else           cp_commit();

    for (int it = 0; it < iters; ++it) {
        cp_wait<2>();
        __syncthreads();

        const int s = it % G_STG;
        const uint32_t a_base = smb + (s * G_ASZ
                              + (wmi * 32 + a_row) * G_ALD + a_col) * 2;
        const uint32_t b_base = smb + (G_STG * G_ASZ + s * G_BSZ
                              + b_row * G_BLD + wni * 64 + b_col) * 2;

#pragma unroll
        for (int ks = 0; ks < 4; ++ks) {
            uint32_t af[2][4];
#pragma unroll
            for (int mi = 0; mi < 2; ++mi)
                ldsm4(af[mi][0], af[mi][1], af[mi][2], af[mi][3],
                      a_base + (mi * 16 * G_ALD + ks * 16) * 2);
            uint32_t bf[4][4];
#pragma unroll
            for (int p = 0; p < 4; ++p)
                ldsm4t(bf[p][0], bf[p][1], bf[p][2], bf[p][3],
                       b_base + (ks * 16 * G_BLD + p * 16) * 2);
#pragma unroll
            for (int mi = 0; mi < 2; ++mi)
#pragma unroll
                for (int p = 0; p < 4; ++p) {
                    mma16816(cfr[mi][2 * p],     af[mi], bf[p][0], bf[p][1]);
                    mma16816(cfr[mi][2 * p + 1], af[mi], bf[p][2], bf[p][3]);
                }
        }
        __syncthreads();

        if (it + 3 < iters) issue_stage(it + 3);
        else                cp_commit();
    }

    // ---- Epilogue ----
    const int nc = n0 & 1023;
    const int colw = wni * 64 + 2 * (lane & 3);
    float2 bv[8];
#pragma unroll
    for (int nt = 0; nt < 8; ++nt) {
        bv[nt].x = bias[n0 + colw + nt * 8];
        bv[nt].y = bias[n0 + colw + nt * 8 + 1];
    }
    const int row0 = m0 + wmi * 32 + (lane >> 2);

    if (ROUND_OUT) {
        __half* outp = (n0 < 1024) ? (__half*)out0v
                     : ((n0 < 2048) ? (__half*)out1v : (__half*)out2v);
        const float osc = (n0 < 1024) ? Q_SCALE : 1.0f;
#pragma unroll
        for (int mi = 0; mi < 2; ++mi) {
#pragma unroll
            for (int nt = 0; nt < 8; ++nt) {
                int col = nc + colw + nt * 8;
                __half2 v0 = __floats2half2_rn((cfr[mi][nt][0] + bv[nt].x) * osc,
                                               (cfr[mi][nt][1] + bv[nt].y) * osc);
                __half2 v1 = __floats2half2_rn((cfr[mi][nt][2] + bv[nt].x) * osc,
                                               (cfr[mi][nt][3] + bv[nt].y) * osc);
                *(__half2*)(outp + (size_t)(row0 + mi * 16) * 1024 + col) = v0;
                *(__half2*)(outp + (size_t)(row0 + mi * 16 + 8) * 1024 + col) = v1;
            }
        }
    } else {
        float* outp = (n0 < 1024) ? (float*)out0v
                    : ((n0 < 2048) ? (float*)out1v : (float*)out2v);
#pragma unroll
        for (int mi = 0; mi < 2; ++mi) {
#pragma unroll
            for (int nt = 0; nt < 8; ++nt) {
                int col = nc + colw + nt * 8;
                float2 v0 = { cfr[mi][nt][0] + bv[nt].x, cfr[mi][nt][1] + bv[nt].y };
                float2 v1 = { cfr[mi][nt][2] + bv[nt].x, cfr[mi][nt][3] + bv[nt].y };
                *(float2*)(outp + (size_t)(row0 + mi * 16) * 1024 + col) = v0;
                *(float2*)(outp + (size_t)(row0 + mi * 16 + 8) * 1024 + col) = v1;
            }
        }
    }
}

// ---------------------------------------------------------------------------
// Flash attention (causal), FA2-style. Br=128, Bc=64, hd=64, 256 thr,
// 2 CTAs/SM, exp2-domain softmax, 3-deep K/V pipeline.
// GLOBAL LPT ordering: 1-D grid of 512, qt descending MAJOR (all heaviest
// tiles across every (b,h) launch first; small tiles backfill freed slots).
// ---------------------------------------------------------------------------
#define FLD 72
#define FQ_OFF  0
#define FK_OFF  18432
#define FV_OFF  (18432 + 27648)
#define F_SMEM  (18432 + 2 * 27648)  // 73728

__global__ __launch_bounds__(256, 2) void flash_fa2_kernel(
    const __half* __restrict__ Qg, const __half* __restrict__ Kg,
    const __half* __restrict__ Vg, __half* __restrict__ yt)
{
    extern __shared__ char smc[];
    const uint32_t smb = smem_u32(smc);
    const uint32_t kbA[3] = { smb + FK_OFF, smb + FK_OFF + 9216, smb + FK_OFF + 18432 };
    const uint32_t vbA[3] = { smb + FV_OFF, smb + FV_OFF + 9216, smb + FV_OFF + 18432 };

    // LPT: qt-descending major, bh minor.  bid 0..31 -> qt=15 (all bh),
    // bid 32..63 -> qt=14, ...  Heaviest CTAs launch first chip-wide.
    const int bid  = blockIdx.x;
    const int qt   = 15 - (bid >> 5);
    const int bh   = bid & 31;
    const int tid  = threadIdx.x;
    const int w    = tid >> 5;
    const int lane = tid & 31;

    const int q_row = (lane & 15);
    const int q_col = (lane >> 4) << 3;
    const int k_row = (lane & 7) + ((lane >> 4) << 3);
    const int k_col = ((lane >> 3) & 1) << 3;
    const int v_row = (lane & 7) + (((lane >> 3) & 1) << 3);
    const int v_col = (lane >> 4) << 3;

    const size_t head_off = (size_t)bh * 131072u;
    const __half* qg = Qg + head_off + (size_t)qt * 8192u;
    const __half* kg = Kg + head_off;
    const __half* vg = Vg + head_off;

#pragma unroll
    for (int t = 0; t < 4; ++t) {
        int f = tid + t * 256;
        int rr = f >> 3, c8 = (f & 7) << 3;
        cp16(smb + FQ_OFF + (rr * FLD + c8) * 2, qg + rr * 64 + c8);
    }
    cp_commit();

    auto issue_kv = [&](int kt) {
        const int buf = kt % 3;
        const __half* kp = kg + (size_t)kt * 4096u;
        const __half* vp = vg + (size_t)kt * 4096u;
#pragma unroll
        for (int t = 0; t < 2; ++t) {
            int f = tid + t * 256;
            int rr = f >> 3, c8 = (f & 7) << 3;
            cp16(kbA[buf] + (rr * FLD + c8) * 2, kp + rr * 64 + c8);
            cp16(vbA[buf] + (rr * FLD + c8) * 2, vp + rr * 64 + c8);
        }
        cp_commit();
    };

    const int n_kt = 2 * (qt + 1);
    issue_kv(0);
    issue_kv(1);
    if (2 < n_kt) issue_kv(2);
    else          cp_commit();

    cp_wait<3>();                // Q resident
    __syncthreads();

    uint32_t qf[4][4];
#pragma unroll
    for (int kk = 0; kk < 4; ++kk) {
        uint32_t a = smb + FQ_OFF
                   + ((w * 16 + q_row) * FLD + kk * 16 + q_col) * 2;
        ldsm4(qf[kk][0], qf[kk][1], qf[kk][2], qf[kk][3], a);
    }

    float oacc[8][4];
#pragma unroll
    for (int nt = 0; nt < 8; ++nt)
#pragma unroll
        for (int j = 0; j < 4; ++j) oacc[nt][j] = 0.0f;
    float m_lo = -1e30f, m_hi = -1e30f;
    float l_lo = 0.0f,   l_hi = 0.0f;

    const int row_g_lo = qt * 128 + w * 16 + (lane >> 2);
    const int row_g_hi = row_g_lo + 8;

    for (int kt = 0; kt < n_kt; ++kt) {
        const int buf = kt % 3;
        cp_wait<2>();
        __syncthreads();

        float sacc[8][4];
#pragma unroll
        for (int nt = 0; nt < 8; ++nt)
#pragma unroll
            for (int j = 0; j < 4; ++j) sacc[nt][j] = 0.0f;
#pragma unroll
        for (int p = 0; p < 4; ++p) {
#pragma unroll
            for (int kk = 0; kk < 4; ++kk) {
                uint32_t b0, b1, b2, b3;
                uint32_t a = kbA[buf]
                           + ((p * 16 + k_row) * FLD + kk * 16 + k_col) * 2;
                ldsm4(b0, b1, b2, b3, a);
                mma16816(sacc[2 * p],     qf[kk], b0, b1);
                mma16816(sacc[2 * p + 1], qf[kk], b2, b3);
            }
        }

        if (kt >= 2 * qt) {
            const int cb = kt * 64 + 2 * (lane & 3);
#pragma unroll
            for (int nt = 0; nt < 8; ++nt) {
                int c = cb + nt * 8;
                if (c     > row_g_lo) sacc[nt][0] = -1e30f;
                if (c + 1 > row_g_lo) sacc[nt][1] = -1e30f;
                if (c     > row_g_hi) sacc[nt][2] = -1e30f;
                if (c + 1 > row_g_hi) sacc[nt][3] = -1e30f;
            }
        }

        float mx_lo = -1e30f, mx_hi = -1e30f;
#pragma unroll
        for (int nt = 0; nt < 8; ++nt) {
            mx_lo = fmaxf(mx_lo, fmaxf(sacc[nt][0], sacc[nt][1]));
            mx_hi = fmaxf(mx_hi, fmaxf(sacc[nt][2], sacc[nt][3]));
        }
        mx_lo = fmaxf(mx_lo, __shfl_xor_sync(0xffffffffu, mx_lo, 1));
        mx_lo = fmaxf(mx_lo, __shfl_xor_sync(0xffffffffu, mx_lo, 2));
        mx_hi = fmaxf(mx_hi, __shfl_xor_sync(0xffffffffu, mx_hi, 1));
        mx_hi = fmaxf(mx_hi, __shfl_xor_sync(0xffffffffu, mx_hi, 2));

        const float mn_lo = fmaxf(m_lo, mx_lo);
        const float mn_hi = fmaxf(m_hi, mx_hi);
        const float al_lo = exp2f(m_lo - mn_lo);
        const float al_hi = exp2f(m_hi - mn_hi);
        m_lo = mn_lo; m_hi = mn_hi;

        float sum_lo = 0.0f, sum_hi = 0.0f;
        uint32_t pfr[4][4];
#pragma unroll
        for (int nt = 0; nt < 8; ++nt) {
            float p0 = exp2f(sacc[nt][0] - mn_lo);
            float p1 = exp2f(sacc[nt][1] - mn_lo);
            float p2 = exp2f(sacc[nt][2] - mn_hi);
            float p3 = exp2f(sacc[nt][3] - mn_hi);
            sum_lo += p0 + p1;
            sum_hi += p2 + p3;
            __half2 h01 = __floats2half2_rn(p0, p1);
            __half2 h23 = __floats2half2_rn(p2, p3);
            pfr[nt >> 1][(nt & 1) * 2 + 0] = *(uint32_t*)&h01;
            pfr[nt >> 1][(nt & 1) * 2 + 1] = *(uint32_t*)&h23;
        }
        l_lo = l_lo * al_lo + sum_lo;
        l_hi = l_hi * al_hi + sum_hi;

#pragma unroll
        for (int nt = 0; nt < 8; ++nt) {
            oacc[nt][0] *= al_lo; oacc[nt][1] *= al_lo;
            oacc[nt][2] *= al_hi; oacc[nt][3] *= al_hi;
        }

#pragma unroll
        for (int p = 0; p < 4; ++p) {
#pragma unroll
            for (int t = 0; t < 4; ++t) {
                uint32_t b0, b1, b2, b3;
                uint32_t a = vbA[buf]
                           + ((t * 16 + v_row) * FLD + p * 16 + v_col) * 2;
                ldsm4t(b0, b1, b2, b3, a);
                mma16816(oacc[2 * p],     pfr[t], b0, b1);
                mma16816(oacc[2 * p + 1], pfr[t], b2, b3);
            }
        }

        __syncthreads();
        if (kt + 3 < n_kt) issue_kv(kt + 3);
        else               cp_commit();
    }

    l_lo += __shfl_xor_sync(0xffffffffu, l_lo, 1);
    l_lo += __shfl_xor_sync(0xffffffffu, l_lo, 2);
    l_hi += __shfl_xor_sync(0xffffffffu, l_hi, 1);
    l_hi += __shfl_xor_sync(0xffffffffu, l_hi, 2);
    const float inv_lo = 1.0f / l_lo;
    const float inv_hi = 1.0f / l_hi;

    const int b = bh >> 4;
    const int h = bh & 15;
    const int tq_lo = qt * 128 + w * 16 + (lane >> 2);
    __half* dst_lo = yt + ((size_t)(b * 2048 + tq_lo)) * 1024u + h * 64 + 2 * (lane & 3);
    __half* dst_hi = dst_lo + 8u * 1024u;
#pragma unroll
    for (int nt = 0; nt < 8; ++nt) {
        __half2 vlo = __floats2half2_rn(oacc[nt][0] * inv_lo, oacc[nt][1] * inv_lo);
        __half2 vhi = __floats2half2_rn(oacc[nt][2] * inv_hi, oacc[nt][3] * inv_hi);
        *(__half2*)(dst_lo + nt * 8) = vlo;
        *(__half2*)(dst_hi + nt * 8) = vhi;
    }
}

// ---------------------------------------------------------------------------
// Launch
// ---------------------------------------------------------------------------
extern "C" void kernel_launch(void* const* d_in, const int* in_sizes, int n_in,
                              void* d_out, int out_size)
{
    const float* x     = (const float*)d_in[0];
    const float* Wqkv  = (const float*)d_in[1];
    const float* bqkv  = (const float*)d_in[2];
    const float* Wproj = (const float*)d_in[3];
    const float* bproj = (const float*)d_in[4];
    float* out = (float*)d_out;

    __half *q, *k, *v, *yt, *xh, *wqkvh, *wprojh;
    cudaGetSymbolAddress((void**)&q,  g_q);
    cudaGetSymbolAddress((void**)&k,  g_k);
    cudaGetSymbolAddress((void**)&v,  g_v);
    cudaGetSymbolAddress((void**)&yt, g_yt);
    cudaGetSymbolAddress((void**)&xh, g_xh);
    cudaGetSymbolAddress((void**)&wqkvh, g_wqkvh);
    cudaGetSymbolAddress((void**)&wprojh, g_wprojh);

    const int M = 4096, C = 1024;

    // 0) fp32 -> fp16 conversion
    {
        to_half3_kernel<<<2048, 256>>>(x, Wqkv, Wproj, xh, wqkvh, wprojh);
    }

    cudaFuncSetAttribute(gemm_mma_kernel<1>,
                         cudaFuncAttributeMaxDynamicSharedMemorySize, G_SMEM_BYTES);
    cudaFuncSetAttribute(gemm_mma_kernel<0>,
                         cudaFuncAttributeMaxDynamicSharedMemorySize, G_SMEM_BYTES);

    // 1) QKV projection -> half q/k/v (Q pre-scaled by 0.125*log2e)
    {
        dim3 grid(3 * C / 128, M / 128);   // (24, 32)
        gemm_mma_kernel<1><<<grid, 256, G_SMEM_BYTES>>>(xh, wqkvh, bqkv,
                                                        q, k, v, M, 3 * C, C);
    }

    // 2) Flash attention (causal) -> yt (half), LPT-ordered 1-D grid
    {
        cudaFuncSetAttribute(flash_fa2_kernel,
                             cudaFuncAttributeMaxDynamicSharedMemorySize, F_SMEM);
        flash_fa2_kernel<<<512, 256, F_SMEM>>>(q, k, v, yt);
    }

    // 3) Output projection -> fp32 out
    {
        dim3 grid(C / 128, M / 128);       // (8, 32)
        gemm_mma_kernel<0><<<grid, 256, G_SMEM_BYTES>>>(yt, wprojh, bproj,
                                                        out, out, out, M, C, C);
    }
}